// round 1
// baseline (speedup 1.0000x reference)
#include <cuda_runtime.h>

#define N_BINS 15

// Global scratch (allocation-free rule: __device__ globals).
__device__ float g_sum_conf[N_BINS];
__device__ float g_sum_corr[N_BINS];

__global__ void ece_zero_kernel() {
    int t = threadIdx.x;
    if (t < N_BINS) {
        g_sum_conf[t] = 0.0f;
        g_sum_corr[t] = 0.0f;
    }
}

__global__ __launch_bounds__(256) void ece_main_kernel(
    const float4* __restrict__ logits,   // [N, 32] float4 view of [N,128] fp32
    const int* __restrict__ labels,      // [N]
    int N)
{
    __shared__ float s_conf[N_BINS];
    __shared__ float s_corr[N_BINS];

    const int t = threadIdx.x;
    if (t < N_BINS) { s_conf[t] = 0.0f; s_corr[t] = 0.0f; }
    __syncthreads();

    const int lane = t & 31;
    const int warp = t >> 5;
    const int warps_per_block = blockDim.x >> 5;

    long long row    = (long long)blockIdx.x * warps_per_block + warp;
    const long long stride = (long long)gridDim.x * warps_per_block;

    for (; row < N; row += stride) {
        // One warp per row: lane l holds cols [4l, 4l+3]. 512B coalesced.
        float4 v = logits[row * 32 + lane];

        // Lane-local max + index (prefer lowest index on tie, like jnp.argmax)
        float m = v.x; int mi = 0;
        if (v.y > m) { m = v.y; mi = 1; }
        if (v.z > m) { m = v.z; mi = 2; }
        if (v.w > m) { m = v.w; mi = 3; }
        int idx = lane * 4 + mi;

        // Warp argmax reduction (lowest index wins ties)
        #pragma unroll
        for (int off = 16; off > 0; off >>= 1) {
            float om = __shfl_xor_sync(0xFFFFFFFFu, m,   off);
            int   oi = __shfl_xor_sync(0xFFFFFFFFu, idx, off);
            if (om > m || (om == m && oi < idx)) { m = om; idx = oi; }
        }

        // Sum of exp(x - max); conf = exp(max - max)/sum = 1/sum
        float s = __expf(v.x - m) + __expf(v.y - m)
                + __expf(v.z - m) + __expf(v.w - m);
        #pragma unroll
        for (int off = 16; off > 0; off >>= 1)
            s += __shfl_xor_sync(0xFFFFFFFFu, s, off);

        if (lane == 0) {
            float conf = 1.0f / s;
            // bin = clip(ceil(conf * 15) - 1, 0, 14)
            int b = (int)ceilf(conf * (float)N_BINS) - 1;
            b = min(max(b, 0), N_BINS - 1);
            atomicAdd(&s_conf[b], conf);
            if (idx == labels[row]) atomicAdd(&s_corr[b], 1.0f);
        }
    }

    __syncthreads();
    if (t < N_BINS) {
        atomicAdd(&g_sum_conf[t], s_conf[t]);
        atomicAdd(&g_sum_corr[t], s_corr[t]);
    }
}

__global__ void ece_finalize_kernel(float* __restrict__ out, float invN) {
    if (threadIdx.x == 0 && blockIdx.x == 0) {
        float e = 0.0f;
        #pragma unroll
        for (int b = 0; b < N_BINS; b++)
            e += fabsf(g_sum_conf[b] - g_sum_corr[b]);
        out[0] = e * invN;
    }
}

extern "C" void kernel_launch(void* const* d_in, const int* in_sizes, int n_in,
                              void* d_out, int out_size)
{
    const float4* logits = (const float4*)d_in[0];  // [N,128] fp32
    const int*    labels = (const int*)d_in[1];     // [N] int32
    float*        out    = (float*)d_out;

    const int N = in_sizes[1];   // number of rows (labels count)

    ece_zero_kernel<<<1, 32>>>();

    // Persistent-ish grid: 8 blocks/SM x 148 SMs, 8 warps (rows) per block/iter
    const int threads = 256;
    int blocks = 1184;
    int warps_needed = N;                       // one warp per row
    int blocks_needed = (warps_needed + 7) / 8; // 8 warps per block
    if (blocks > blocks_needed) blocks = blocks_needed;
    if (blocks < 1) blocks = 1;

    ece_main_kernel<<<blocks, threads>>>(logits, labels, N);

    ece_finalize_kernel<<<1, 32>>>(out, 1.0f / (float)N);
}

// round 2
// speedup vs baseline: 1.9899x; 1.9899x over previous
#include <cuda_runtime.h>

#define N_BINS 15

__device__ float g_sum_conf[N_BINS];
__device__ float g_sum_corr[N_BINS];

__global__ void ece_zero_kernel() {
    int t = threadIdx.x;
    if (t < N_BINS) {
        g_sum_conf[t] = 0.0f;
        g_sum_corr[t] = 0.0f;
    }
}

// 4 threads per row ("quad"), 8 rows per warp, 64 rows per 256-thread block.
// Thread p of a quad loads float4 indices {p, p+4, p+8, ..., p+28} of its row
// (each quad reads contiguous 64B segments -> fully coalesced, MLP=8/thread).
__global__ __launch_bounds__(256) void ece_main_kernel(
    const float4* __restrict__ logits,   // [N, 32] float4 view of [N,128] fp32
    const int* __restrict__ labels,      // [N]
    int N)
{
    __shared__ float s_conf[N_BINS];
    __shared__ float s_corr[N_BINS];

    const int t = threadIdx.x;
    if (t < N_BINS) { s_conf[t] = 0.0f; s_corr[t] = 0.0f; }
    __syncthreads();

    const int lane = t & 31;
    const int warp = t >> 5;
    const int p    = lane & 3;    // position within quad (0..3)
    const int r    = lane >> 2;   // row within warp (0..7)

    const int row  = blockIdx.x * 64 + warp * 8 + r;
    const int rowc = min(row, N - 1);   // clamp for safe (possibly duplicate) loads

    // Load all 32 logits of this row slice: 8 independent float4 loads.
    const float4* base = logits + (long long)rowc * 32 + p;
    float4 v[8];
    #pragma unroll
    for (int i = 0; i < 8; i++) v[i] = base[i * 4];

    // Local max + column index (ascending column order => lowest index on ties)
    float m  = v[0].x;
    int   id = 4 * p;           // col(i,c) = 16*i + 4*p + c
    #pragma unroll
    for (int i = 0; i < 8; i++) {
        const float x[4] = { v[i].x, v[i].y, v[i].z, v[i].w };
        #pragma unroll
        for (int c = 0; c < 4; c++) {
            if (i == 0 && c == 0) continue;
            float xv = x[c];
            int col = 16 * i + 4 * p + c;
            if (xv > m) { m = xv; id = col; }
        }
    }

    // Quad argmax reduction (2 levels; lowest column wins ties)
    #pragma unroll
    for (int off = 1; off <= 2; off <<= 1) {
        float om = __shfl_xor_sync(0xFFFFFFFFu, m,  off);
        int   oi = __shfl_xor_sync(0xFFFFFFFFu, id, off);
        if (om > m || (om == m && oi < id)) { m = om; id = oi; }
    }

    // Sum of exp(x - row_max); includes exp(0)=1 for the max element.
    float s = 0.0f;
    #pragma unroll
    for (int i = 0; i < 8; i++) {
        s += __expf(v[i].x - m);
        s += __expf(v[i].y - m);
        s += __expf(v[i].z - m);
        s += __expf(v[i].w - m);
    }
    // Quad sum reduction (2 levels)
    s += __shfl_xor_sync(0xFFFFFFFFu, s, 1);
    s += __shfl_xor_sync(0xFFFFFFFFu, s, 2);

    if (p == 0 && row < N) {
        float conf = 1.0f / s;
        int b = (int)ceilf(conf * (float)N_BINS) - 1;
        b = min(max(b, 0), N_BINS - 1);
        atomicAdd(&s_conf[b], conf);
        if (id == labels[row]) atomicAdd(&s_corr[b], 1.0f);
    }

    __syncthreads();
    if (t < N_BINS) {
        atomicAdd(&g_sum_conf[t], s_conf[t]);
        atomicAdd(&g_sum_corr[t], s_corr[t]);
    }
}

__global__ void ece_finalize_kernel(float* __restrict__ out, float invN) {
    if (threadIdx.x == 0 && blockIdx.x == 0) {
        float e = 0.0f;
        #pragma unroll
        for (int b = 0; b < N_BINS; b++)
            e += fabsf(g_sum_conf[b] - g_sum_corr[b]);
        out[0] = e * invN;
    }
}

extern "C" void kernel_launch(void* const* d_in, const int* in_sizes, int n_in,
                              void* d_out, int out_size)
{
    const float4* logits = (const float4*)d_in[0];
    const int*    labels = (const int*)d_in[1];
    float*        out    = (float*)d_out;

    const int N = in_sizes[1];   // rows = label count

    ece_zero_kernel<<<1, 32>>>();

    int blocks = (N + 63) / 64;   // 64 rows per 256-thread block
    ece_main_kernel<<<blocks, 256>>>(logits, labels, N);

    ece_finalize_kernel<<<1, 32>>>(out, 1.0f / (float)N);
}